// round 16
// baseline (speedup 1.0000x reference)
#include <cuda_runtime.h>
#include <cuda_fp16.h>
#include <cstdint>

// Problem constants
#define MB   8192      // batch rows (M)
#define NB   4096      // 4*H (N)
#define KB   2048      // In + H (K, logical concat)
#define HD   1024

// GEMM tiling (fp16 mma.sync m16n8k16 + ldmatrix + cp.async) — best config
#define BM   128
#define BN   256
#define BK   64        // 64 fp16 = 128 bytes per SMEM row (SW128 atom)
#define STAGES 4
#define NTHREADS 512   // 16 warps, warp grid 2(M) x 8(N), warptile 64x32

#define A_BYTES     (BM * 128)                 // 16384
#define B_BYTES     (BN * 128)                 // 32768
#define STAGE_BYTES (A_BYTES + B_BYTES)        // 49152
#define SMEM_TOTAL  (STAGES * STAGE_BYTES)     // 196608

// scratch: fp16 pre-activations (bias included) + fp16 copies of inputs/weights
__device__ __half g_v16[(size_t)MB * NB];              // 67 MB
__device__ __half g_x16[(size_t)MB * 1024];            // 16 MB
__device__ __half g_h16[(size_t)MB * 1024];            // 16 MB
__device__ __half g_wih16[(size_t)NB * 1024];          // 8 MB
__device__ __half g_whh16[(size_t)NB * 1024];          // 8 MB

// ---------------- helpers ----------------
__device__ __forceinline__ uint32_t smem_u32(const void* p) {
    uint32_t a;
    asm("{ .reg .u64 t; cvta.to.shared.u64 t, %1; cvt.u32.u64 %0, t; }" : "=r"(a) : "l"(p));
    return a;
}
__device__ __forceinline__ void cp16(uint32_t dst, const void* src) {
    asm volatile("cp.async.cg.shared.global [%0], [%1], 16;" :: "r"(dst), "l"(src));
}
#define CP_COMMIT() asm volatile("cp.async.commit_group;" ::: "memory")
#define CP_WAIT2()  asm volatile("cp.async.wait_group 2;" ::: "memory")

__device__ __forceinline__ void ldsm4(uint32_t* r, uint32_t a) {
    asm volatile("ldmatrix.sync.aligned.m8n8.x4.shared.b16 {%0,%1,%2,%3}, [%4];"
        : "=r"(r[0]), "=r"(r[1]), "=r"(r[2]), "=r"(r[3]) : "r"(a));
}
__device__ __forceinline__ void mma_f16(float* d, const uint32_t* a, const uint32_t* b) {
    asm volatile(
        "mma.sync.aligned.m16n8k16.row.col.f32.f16.f16.f32 "
        "{%0,%1,%2,%3}, {%4,%5,%6,%7}, {%8,%9}, {%0,%1,%2,%3};"
        : "+f"(d[0]), "+f"(d[1]), "+f"(d[2]), "+f"(d[3])
        : "r"(a[0]), "r"(a[1]), "r"(a[2]), "r"(a[3]), "r"(b[0]), "r"(b[1]));
}
// SW128 swizzle on byte offset (row*128 + chunk*16)
__device__ __forceinline__ uint32_t swz(uint32_t o) { return o ^ ((o >> 3) & 0x70); }

// ---------------- fp32 -> fp16 conversion pre-pass (block-segmented, 4x MLP) ----------------
#define N4_XH (MB * 1024 / 4)   // 2M float4
#define N4_W  (NB * 1024 / 4)   // 1M float4
__global__ void __launch_bounds__(512)
cvt_all_kernel(const float4* __restrict__ x, const float4* __restrict__ h,
               const float4* __restrict__ wih, const float4* __restrict__ whh)
{
    const int bid = blockIdx.x;
    const float4* src;
    uint2* dst;
    int n4, b0, nb;
    if (bid < 512)        { src = x;   dst = (uint2*)g_x16;   n4 = N4_XH; b0 = bid;        nb = 512; }
    else if (bid < 1024)  { src = h;   dst = (uint2*)g_h16;   n4 = N4_XH; b0 = bid - 512;  nb = 512; }
    else if (bid < 1280)  { src = wih; dst = (uint2*)g_wih16; n4 = N4_W;  b0 = bid - 1024; nb = 256; }
    else                  { src = whh; dst = (uint2*)g_whh16; n4 = N4_W;  b0 = bid - 1280; nb = 256; }
    for (int base = b0 * 2048 + threadIdx.x; base < n4; base += nb * 2048) {
        float4 f0 = src[base];
        float4 f1 = src[base + 512];
        float4 f2 = src[base + 1024];
        float4 f3 = src[base + 1536];
        uint2 o0, o1, o2, o3;
        { __half2 a = __floats2half2_rn(f0.x, f0.y), b = __floats2half2_rn(f0.z, f0.w);
          o0.x = *reinterpret_cast<uint32_t*>(&a); o0.y = *reinterpret_cast<uint32_t*>(&b); }
        { __half2 a = __floats2half2_rn(f1.x, f1.y), b = __floats2half2_rn(f1.z, f1.w);
          o1.x = *reinterpret_cast<uint32_t*>(&a); o1.y = *reinterpret_cast<uint32_t*>(&b); }
        { __half2 a = __floats2half2_rn(f2.x, f2.y), b = __floats2half2_rn(f2.z, f2.w);
          o2.x = *reinterpret_cast<uint32_t*>(&a); o2.y = *reinterpret_cast<uint32_t*>(&b); }
        { __half2 a = __floats2half2_rn(f3.x, f3.y), b = __floats2half2_rn(f3.z, f3.w);
          o3.x = *reinterpret_cast<uint32_t*>(&a); o3.y = *reinterpret_cast<uint32_t*>(&b); }
        dst[base]        = o0;
        dst[base + 512]  = o1;
        dst[base + 1024] = o2;
        dst[base + 1536] = o3;
    }
}

// ---------------- GEMM ----------------
// grid (NB/BN=16, MB/BM=64), 512 threads = 16 warps, warptile 64x32
// Epilogue fuses the b_ih bias add (fp32, pre-quantization).
__global__ void __launch_bounds__(NTHREADS, 1)
gemm_f16_kernel(const float* __restrict__ b_ih)
{
    extern __shared__ char smem[];
    const uint32_t sb = smem_u32(smem);
    const int tid = threadIdx.x, warp = tid >> 5, lane = tid & 31;
    const int bm = blockIdx.y * BM;
    const int bn = blockIdx.x * BN;
    const int wm = (warp & 1) * 64;       // 2 warp rows
    const int wn = (warp >> 1) * 32;      // 8 warp cols
    const int g  = lane >> 3, L = lane & 7;     // ldmatrix lane-group / row-in-group

    // issue one stage of cp.async loads (tile t -> slot t&3)
    auto issue = [&](int t) {
        const int s = t & 3;
        const __half *As, *Bs;
        int kk;
        if (t < 16) { As = g_x16; Bs = g_wih16; kk = t * BK; }
        else        { As = g_h16; Bs = g_whh16; kk = t * BK - 1024; }
        const uint32_t abase = sb + s * STAGE_BYTES;
        const uint32_t bbase = abase + A_BYTES;
        #pragma unroll
        for (int i = 0; i < 2; i++) {           // A: 128 rows x 8 chunks = 1024
            const int id = tid + NTHREADS * i, r = id >> 3, c = id & 7;
            cp16(abase + swz((uint32_t)(r * 128 + c * 16)),
                 As + (size_t)(bm + r) * 1024 + kk + c * 8);
        }
        #pragma unroll
        for (int i = 0; i < 4; i++) {           // B: 256 rows x 8 chunks = 2048
            const int id = tid + NTHREADS * i, r = id >> 3, c = id & 7;
            cp16(bbase + swz((uint32_t)(r * 128 + c * 16)),
                 Bs + (size_t)(bn + r) * 1024 + kk + c * 8);
        }
    };

    float acc[4][4][4];   // mt (4 x m16), nt (4 x n8), frag
    #pragma unroll
    for (int i = 0; i < 4; i++)
        #pragma unroll
        for (int j = 0; j < 4; j++)
            #pragma unroll
            for (int k = 0; k < 4; k++) acc[i][j][k] = 0.f;

    issue(0); CP_COMMIT();
    issue(1); CP_COMMIT();
    issue(2); CP_COMMIT();

    const int T = KB / BK;   // 32
    for (int t = 0; t < T; t++) {
        const int s = t & 3;
        CP_WAIT2();
        __syncthreads();
        // Issue next stage first: the barrier guarantees every warp finished
        // reading slot (t-1)&3 last iteration, so overwriting it is safe and
        // the LSU work overlaps this iteration's MMAs.
        if (t + 3 < T) issue(t + 3);
        CP_COMMIT();    // unconditional: keeps wait_group accounting exact

        const uint32_t abase = sb + s * STAGE_BYTES;
        const uint32_t bbase = abase + A_BYTES;

        #pragma unroll
        for (int ks = 0; ks < 4; ks++) {        // 4 x k16 per BK=64
            uint32_t af[4][4], bf[2][4];
            #pragma unroll
            for (int mt = 0; mt < 4; mt++) {
                const int row = wm + mt * 16 + (g & 1) * 8 + L;
                const int ch  = 2 * ks + (g >> 1);
                ldsm4(af[mt], abase + swz((uint32_t)(row * 128 + ch * 16)));
            }
            #pragma unroll
            for (int p = 0; p < 2; p++) {
                const int row = wn + p * 16 + (g >> 1) * 8 + L;
                const int ch  = 2 * ks + (g & 1);
                ldsm4(bf[p], bbase + swz((uint32_t)(row * 128 + ch * 16)));
            }
            #pragma unroll
            for (int mt = 0; mt < 4; mt++)
                #pragma unroll
                for (int p = 0; p < 2; p++) {
                    mma_f16(acc[mt][2 * p],     af[mt], &bf[p][0]);   // n8 lo: {r0,r1}
                    mma_f16(acc[mt][2 * p + 1], af[mt], &bf[p][2]);   // n8 hi: {r2,r3}
                }
        }
    }

    // epilogue: thread (q,tq): c0,c1 at (row+q, col+2tq), c2,c3 at row+q+8.
    // Fused b_ih add (columns identical for both rows of a frag).
    const int q = lane >> 2, tq = lane & 3;
    float2 bias[4];
    #pragma unroll
    for (int nt = 0; nt < 4; nt++)
        bias[nt] = *reinterpret_cast<const float2*>(&b_ih[bn + wn + nt * 8 + 2 * tq]);
    #pragma unroll
    for (int mt = 0; mt < 4; mt++) {
        const int rg = bm + wm + mt * 16 + q;
        #pragma unroll
        for (int nt = 0; nt < 4; nt++) {
            const int cg = bn + wn + nt * 8 + 2 * tq;
            __half2 lo = __floats2half2_rn(acc[mt][nt][0] + bias[nt].x,
                                           acc[mt][nt][1] + bias[nt].y);
            __half2 hi = __floats2half2_rn(acc[mt][nt][2] + bias[nt].x,
                                           acc[mt][nt][3] + bias[nt].y);
            *reinterpret_cast<__half2*>(&g_v16[(size_t)rg * NB + cg])       = lo;
            *reinterpret_cast<__half2*>(&g_v16[(size_t)(rg + 8) * NB + cg]) = hi;
        }
    }
}

// ---------------- LayerNorm-LSTM pointwise kernel ----------------
// 512 threads = 2 independent 256-thread row-groups with NAMED barriers:
// each group's 4 barriers sync only its own 8 warps, and the two rows'
// stalls interleave on the SM (better issue coverage). Per-thread work,
// registers and instruction stream identical to the round-15 version.
__device__ __forceinline__ float ftanh(float x) {
    float r;
    asm("tanh.approx.f32 %0, %1;" : "=f"(r) : "f"(x));
    return r;
}
__device__ __forceinline__ float fsig(float x) {
    return fmaf(0.5f, ftanh(0.5f * x), 0.5f);   // sigmoid via HW tanh
}
#define GBAR(id) asm volatile("bar.sync %0, 256;" :: "r"(id) : "memory")

__global__ __launch_bounds__(512, 4)
void ln_lstm_kernel(const float* __restrict__ cprev,
                    const float* __restrict__ gamma_ifgo, const float* __restrict__ beta_ifgo,
                    const float* __restrict__ gamma_c,    const float* __restrict__ beta_c,
                    float* __restrict__ out_h, float* __restrict__ out_c)
{
    const float EPS = 1e-6f;
    const int half = threadIdx.x >> 8;          // 0 or 1: which row this thread works on
    const int tid  = threadIdx.x & 255;         // index within the row-group
    const int b    = blockIdx.x * 2 + half;
    const int warp = tid >> 5, lane = tid & 31;
    const int barid = 1 + half;                 // named barrier id per group

    const uint2* vb2 = reinterpret_cast<const uint2*>(g_v16 + (size_t)b * NB);
    const float4* ga4 = reinterpret_cast<const float4*>(gamma_ifgo);
    const float4* be4 = reinterpret_cast<const float4*>(beta_ifgo);
    const float4* gc4 = reinterpret_cast<const float4*>(gamma_c);
    const float4* bc4 = reinterpret_cast<const float4*>(beta_c);
    const float4* cp4 = reinterpret_cast<const float4*>(cprev) + (size_t)b * 256;
    float4* oh4 = reinterpret_cast<float4*>(out_h) + (size_t)b * 256;
    float4* oc4 = reinterpret_cast<float4*>(out_c) + (size_t)b * 256;

    float4 val[4];
    float s[4], q[4];
    #pragma unroll
    for (int g = 0; g < 4; g++) {
        uint2 raw = vb2[g * 256 + tid];
        float2 p01 = __half22float2(*reinterpret_cast<__half2*>(&raw.x));
        float2 p23 = __half22float2(*reinterpret_cast<__half2*>(&raw.y));
        float4 v = make_float4(p01.x, p01.y, p23.x, p23.y);
        val[g] = v;
        s[g] = v.x + v.y + v.z + v.w;
        q[g] = v.x * v.x + v.y * v.y + v.z * v.z + v.w * v.w;
    }

    __shared__ float red[2][8][8];
    __shared__ float red2[2][8][2];
    __shared__ float mean_s[2][4], inv_s[2][4];
    __shared__ float meanc_s[2], invc_s[2];

    #pragma unroll
    for (int g = 0; g < 4; g++)
        #pragma unroll
        for (int off = 16; off; off >>= 1) {
            s[g] += __shfl_xor_sync(0xffffffffu, s[g], off);
            q[g] += __shfl_xor_sync(0xffffffffu, q[g], off);
        }
    if (lane == 0) {
        #pragma unroll
        for (int g = 0; g < 4; g++) { red[half][warp][g] = s[g]; red[half][warp][g + 4] = q[g]; }
    }
    GBAR(barid);
    if (tid < 4) {
        float ts = 0.f, tq2 = 0.f;
        #pragma unroll
        for (int w = 0; w < 8; w++) { ts += red[half][w][tid]; tq2 += red[half][w][tid + 4]; }
        float mean = ts * (1.f / HD);
        float var  = (tq2 - (float)HD * mean * mean) * (1.f / (HD - 1));
        var = fmaxf(var, 0.f);
        mean_s[half][tid] = mean;
        inv_s[half][tid]  = 1.f / (sqrtf(var) + EPS);
    }
    GBAR(barid);

    float4 gam[4], bet[4];
    #pragma unroll
    for (int g = 0; g < 4; g++) { gam[g] = ga4[g * 256 + tid]; bet[g] = be4[g * 256 + tid]; }
    const float4 cpv = cp4[tid];

    float ivals[4], fvals[4], gvals[4], ovals[4];
    {
        const float m0 = mean_s[half][0], m1 = mean_s[half][1];
        const float m2 = mean_s[half][2], m3 = mean_s[half][3];
        const float i0 = inv_s[half][0],  i1 = inv_s[half][1];
        const float i2 = inv_s[half][2],  i3 = inv_s[half][3];
        const float* v0 = &val[0].x; const float* v1 = &val[1].x;
        const float* v2 = &val[2].x; const float* v3 = &val[3].x;
        const float* g0 = &gam[0].x; const float* g1 = &gam[1].x;
        const float* g2 = &gam[2].x; const float* g3 = &gam[3].x;
        const float* b0 = &bet[0].x; const float* b1 = &bet[1].x;
        const float* b2 = &bet[2].x; const float* b3 = &bet[3].x;
        #pragma unroll
        for (int e = 0; e < 4; e++) {
            ivals[e] = (v0[e] - m0) * i0 * g0[e] + b0[e];
            fvals[e] = (v1[e] - m1) * i1 * g1[e] + b1[e] + 1.0f;
            gvals[e] = (v2[e] - m2) * i2 * g2[e] + b2[e];
            ovals[e] = (v3[e] - m3) * i3 * g3[e] + b3[e];
        }
    }

    float nc[4];
    float cs = 0.f, cq = 0.f;
    const float* cpe = &cpv.x;
    #pragma unroll
    for (int e = 0; e < 4; e++) {
        float ncr = cpe[e] * fsig(fvals[e]) + fsig(ivals[e]) * ftanh(gvals[e]);
        nc[e] = ncr;
        cs += ncr;
        cq += ncr * ncr;
    }

    #pragma unroll
    for (int off = 16; off; off >>= 1) {
        cs += __shfl_xor_sync(0xffffffffu, cs, off);
        cq += __shfl_xor_sync(0xffffffffu, cq, off);
    }
    if (lane == 0) { red2[half][warp][0] = cs; red2[half][warp][1] = cq; }
    GBAR(barid);
    if (tid == 0) {
        float ts = 0.f, tq2 = 0.f;
        #pragma unroll
        for (int w = 0; w < 8; w++) { ts += red2[half][w][0]; tq2 += red2[half][w][1]; }
        float mean = ts * (1.f / HD);
        float var  = (tq2 - (float)HD * mean * mean) * (1.f / (HD - 1));
        var = fmaxf(var, 0.f);
        meanc_s[half] = mean;
        invc_s[half]  = 1.f / (sqrtf(var) + EPS);
    }
    GBAR(barid);
    const float mc = meanc_s[half], ic = invc_s[half];

    const float4 gcv = gc4[tid], bcv = bc4[tid];
    const float* gce = &gcv.x; const float* bce = &bcv.x;
    float4 outc, outh;
    float* ocp = &outc.x; float* ohp = &outh.x;
    #pragma unroll
    for (int e = 0; e < 4; e++) {
        float ncn = (nc[e] - mc) * ic * gce[e] + bce[e];
        ocp[e] = ncn;
        ohp[e] = ftanh(ncn) * fsig(ovals[e]);
    }
    oc4[tid] = outc;
    oh4[tid] = outh;
}

extern "C" void kernel_launch(void* const* d_in, const int* in_sizes, int n_in,
                              void* d_out, int out_size)
{
    const float* x          = (const float*)d_in[0];
    const float* h          = (const float*)d_in[1];
    const float* c          = (const float*)d_in[2];
    const float* w_ih       = (const float*)d_in[3];
    const float* b_ih       = (const float*)d_in[4];
    const float* w_hh       = (const float*)d_in[5];
    const float* gamma_ifgo = (const float*)d_in[6];
    const float* beta_ifgo  = (const float*)d_in[7];
    const float* gamma_c    = (const float*)d_in[8];
    const float* beta_c     = (const float*)d_in[9];

    float* out_h = (float*)d_out;
    float* out_c = out_h + (size_t)MB * HD;

    cudaFuncSetAttribute(gemm_f16_kernel,
                         cudaFuncAttributeMaxDynamicSharedMemorySize, SMEM_TOTAL);

    cvt_all_kernel<<<1536, 512>>>((const float4*)x, (const float4*)h,
                                  (const float4*)w_ih, (const float4*)w_hh);

    dim3 ggrid(NB / BN, MB / BM);   // 16 x 64
    gemm_f16_kernel<<<ggrid, NTHREADS, SMEM_TOTAL>>>(b_ih);
    ln_lstm_kernel<<<MB / 2, 512>>>(c, gamma_ifgo, beta_ifgo, gamma_c, beta_c, out_h, out_c);
}

// round 17
// speedup vs baseline: 1.0158x; 1.0158x over previous
#include <cuda_runtime.h>
#include <cuda_fp16.h>
#include <cstdint>

// Problem constants
#define MB   8192      // batch rows (M)
#define NB   4096      // 4*H (N)
#define KB   2048      // In + H (K, logical concat)
#define HD   1024

// GEMM tiling (fp16 mma.sync m16n8k16 + ldmatrix + cp.async) — best config
#define BM   128
#define BN   256
#define BK   64        // 64 fp16 = 128 bytes per SMEM row (SW128 atom)
#define STAGES 4
#define NTHREADS 512   // 16 warps, warp grid 2(M) x 8(N), warptile 64x32

#define A_BYTES     (BM * 128)                 // 16384
#define B_BYTES     (BN * 128)                 // 32768
#define STAGE_BYTES (A_BYTES + B_BYTES)        // 49152
#define SMEM_TOTAL  (STAGES * STAGE_BYTES)     // 196608

// epilogue staging: 128 rows x 264 halfs (8-half pad -> conflict-free STS), 67.6 KB
#define ORS  264

// scratch: fp16 pre-activations (bias included) + fp16 copies of inputs/weights
__device__ __half g_v16[(size_t)MB * NB];              // 67 MB
__device__ __half g_x16[(size_t)MB * 1024];            // 16 MB
__device__ __half g_h16[(size_t)MB * 1024];            // 16 MB
__device__ __half g_wih16[(size_t)NB * 1024];          // 8 MB
__device__ __half g_whh16[(size_t)NB * 1024];          // 8 MB

// ---------------- helpers ----------------
__device__ __forceinline__ uint32_t smem_u32(const void* p) {
    uint32_t a;
    asm("{ .reg .u64 t; cvta.to.shared.u64 t, %1; cvt.u32.u64 %0, t; }" : "=r"(a) : "l"(p));
    return a;
}
__device__ __forceinline__ void cp16(uint32_t dst, const void* src) {
    asm volatile("cp.async.cg.shared.global [%0], [%1], 16;" :: "r"(dst), "l"(src));
}
#define CP_COMMIT() asm volatile("cp.async.commit_group;" ::: "memory")
#define CP_WAIT2()  asm volatile("cp.async.wait_group 2;" ::: "memory")

__device__ __forceinline__ void ldsm4(uint32_t* r, uint32_t a) {
    asm volatile("ldmatrix.sync.aligned.m8n8.x4.shared.b16 {%0,%1,%2,%3}, [%4];"
        : "=r"(r[0]), "=r"(r[1]), "=r"(r[2]), "=r"(r[3]) : "r"(a));
}
__device__ __forceinline__ void mma_f16(float* d, const uint32_t* a, const uint32_t* b) {
    asm volatile(
        "mma.sync.aligned.m16n8k16.row.col.f32.f16.f16.f32 "
        "{%0,%1,%2,%3}, {%4,%5,%6,%7}, {%8,%9}, {%0,%1,%2,%3};"
        : "+f"(d[0]), "+f"(d[1]), "+f"(d[2]), "+f"(d[3])
        : "r"(a[0]), "r"(a[1]), "r"(a[2]), "r"(a[3]), "r"(b[0]), "r"(b[1]));
}
// SW128 swizzle on byte offset (row*128 + chunk*16)
__device__ __forceinline__ uint32_t swz(uint32_t o) { return o ^ ((o >> 3) & 0x70); }

// ---------------- fp32 -> fp16 conversion pre-pass (block-segmented, 4x MLP) ----------------
#define N4_XH (MB * 1024 / 4)   // 2M float4
#define N4_W  (NB * 1024 / 4)   // 1M float4
__global__ void __launch_bounds__(512)
cvt_all_kernel(const float4* __restrict__ x, const float4* __restrict__ h,
               const float4* __restrict__ wih, const float4* __restrict__ whh)
{
    const int bid = blockIdx.x;
    const float4* src;
    uint2* dst;
    int n4, b0, nb;
    if (bid < 512)        { src = x;   dst = (uint2*)g_x16;   n4 = N4_XH; b0 = bid;        nb = 512; }
    else if (bid < 1024)  { src = h;   dst = (uint2*)g_h16;   n4 = N4_XH; b0 = bid - 512;  nb = 512; }
    else if (bid < 1280)  { src = wih; dst = (uint2*)g_wih16; n4 = N4_W;  b0 = bid - 1024; nb = 256; }
    else                  { src = whh; dst = (uint2*)g_whh16; n4 = N4_W;  b0 = bid - 1280; nb = 256; }
    for (int base = b0 * 2048 + threadIdx.x; base < n4; base += nb * 2048) {
        float4 f0 = src[base];
        float4 f1 = src[base + 512];
        float4 f2 = src[base + 1024];
        float4 f3 = src[base + 1536];
        uint2 o0, o1, o2, o3;
        { __half2 a = __floats2half2_rn(f0.x, f0.y), b = __floats2half2_rn(f0.z, f0.w);
          o0.x = *reinterpret_cast<uint32_t*>(&a); o0.y = *reinterpret_cast<uint32_t*>(&b); }
        { __half2 a = __floats2half2_rn(f1.x, f1.y), b = __floats2half2_rn(f1.z, f1.w);
          o1.x = *reinterpret_cast<uint32_t*>(&a); o1.y = *reinterpret_cast<uint32_t*>(&b); }
        { __half2 a = __floats2half2_rn(f2.x, f2.y), b = __floats2half2_rn(f2.z, f2.w);
          o2.x = *reinterpret_cast<uint32_t*>(&a); o2.y = *reinterpret_cast<uint32_t*>(&b); }
        { __half2 a = __floats2half2_rn(f3.x, f3.y), b = __floats2half2_rn(f3.z, f3.w);
          o3.x = *reinterpret_cast<uint32_t*>(&a); o3.y = *reinterpret_cast<uint32_t*>(&b); }
        dst[base]        = o0;
        dst[base + 512]  = o1;
        dst[base + 1024] = o2;
        dst[base + 1536] = o3;
    }
}

// ---------------- GEMM ----------------
// grid (NB/BN=16, MB/BM=64), 512 threads = 16 warps, warptile 64x32
// Epilogue: fused b_ih bias (fp32) + SMEM-staged coalesced fp16 stores.
__global__ void __launch_bounds__(NTHREADS, 1)
gemm_f16_kernel(const float* __restrict__ b_ih)
{
    extern __shared__ char smem[];
    const uint32_t sb = smem_u32(smem);
    const int tid = threadIdx.x, warp = tid >> 5, lane = tid & 31;
    const int bm = blockIdx.y * BM;
    const int bn = blockIdx.x * BN;
    const int wm = (warp & 1) * 64;       // 2 warp rows
    const int wn = (warp >> 1) * 32;      // 8 warp cols
    const int g  = lane >> 3, L = lane & 7;     // ldmatrix lane-group / row-in-group

    // issue one stage of cp.async loads (tile t -> slot t&3)
    auto issue = [&](int t) {
        const int s = t & 3;
        const __half *As, *Bs;
        int kk;
        if (t < 16) { As = g_x16; Bs = g_wih16; kk = t * BK; }
        else        { As = g_h16; Bs = g_whh16; kk = t * BK - 1024; }
        const uint32_t abase = sb + s * STAGE_BYTES;
        const uint32_t bbase = abase + A_BYTES;
        #pragma unroll
        for (int i = 0; i < 2; i++) {           // A: 128 rows x 8 chunks = 1024
            const int id = tid + NTHREADS * i, r = id >> 3, c = id & 7;
            cp16(abase + swz((uint32_t)(r * 128 + c * 16)),
                 As + (size_t)(bm + r) * 1024 + kk + c * 8);
        }
        #pragma unroll
        for (int i = 0; i < 4; i++) {           // B: 256 rows x 8 chunks = 2048
            const int id = tid + NTHREADS * i, r = id >> 3, c = id & 7;
            cp16(bbase + swz((uint32_t)(r * 128 + c * 16)),
                 Bs + (size_t)(bn + r) * 1024 + kk + c * 8);
        }
    };

    float acc[4][4][4];   // mt (4 x m16), nt (4 x n8), frag
    #pragma unroll
    for (int i = 0; i < 4; i++)
        #pragma unroll
        for (int j = 0; j < 4; j++)
            #pragma unroll
            for (int k = 0; k < 4; k++) acc[i][j][k] = 0.f;

    issue(0); CP_COMMIT();
    issue(1); CP_COMMIT();
    issue(2); CP_COMMIT();

    const int T = KB / BK;   // 32
    for (int t = 0; t < T; t++) {
        const int s = t & 3;
        CP_WAIT2();
        __syncthreads();
        // Issue next stage first: the barrier guarantees every warp finished
        // reading slot (t-1)&3 last iteration, so overwriting it is safe and
        // the LSU work overlaps this iteration's MMAs.
        if (t + 3 < T) issue(t + 3);
        CP_COMMIT();    // unconditional: keeps wait_group accounting exact

        const uint32_t abase = sb + s * STAGE_BYTES;
        const uint32_t bbase = abase + A_BYTES;

        #pragma unroll
        for (int ks = 0; ks < 4; ks++) {        // 4 x k16 per BK=64
            uint32_t af[4][4], bf[2][4];
            #pragma unroll
            for (int mt = 0; mt < 4; mt++) {
                const int row = wm + mt * 16 + (g & 1) * 8 + L;
                const int ch  = 2 * ks + (g >> 1);
                ldsm4(af[mt], abase + swz((uint32_t)(row * 128 + ch * 16)));
            }
            #pragma unroll
            for (int p = 0; p < 2; p++) {
                const int row = wn + p * 16 + (g >> 1) * 8 + L;
                const int ch  = 2 * ks + (g & 1);
                ldsm4(bf[p], bbase + swz((uint32_t)(row * 128 + ch * 16)));
            }
            #pragma unroll
            for (int mt = 0; mt < 4; mt++)
                #pragma unroll
                for (int p = 0; p < 2; p++) {
                    mma_f16(acc[mt][2 * p],     af[mt], &bf[p][0]);   // n8 lo: {r0,r1}
                    mma_f16(acc[mt][2 * p + 1], af[mt], &bf[p][2]);   // n8 hi: {r2,r3}
                }
        }
    }

    // ---- epilogue: bias + SMEM staging + coalesced write-out ----
    // Stage the 128x256 fp16 tile in SMEM (row stride 264 halfs: STS lane
    // word-index = 132*q + tq -> banks 4q+tq, all 32 distinct, conflict-free),
    // then write 16B-coalesced rows (512B contiguous per warp) to gmem.
    __syncthreads();   // all warps done reading pipeline SMEM
    __half* sv = reinterpret_cast<__half*>(smem);
    const int q = lane >> 2, tq = lane & 3;
    float2 bias[4];
    #pragma unroll
    for (int nt = 0; nt < 4; nt++)
        bias[nt] = *reinterpret_cast<const float2*>(&b_ih[bn + wn + nt * 8 + 2 * tq]);
    #pragma unroll
    for (int mt = 0; mt < 4; mt++) {
        const int r0 = wm + mt * 16 + q;
        #pragma unroll
        for (int nt = 0; nt < 4; nt++) {
            const int col = wn + nt * 8 + 2 * tq;
            __half2 lo = __floats2half2_rn(acc[mt][nt][0] + bias[nt].x,
                                           acc[mt][nt][1] + bias[nt].y);
            __half2 hi = __floats2half2_rn(acc[mt][nt][2] + bias[nt].x,
                                           acc[mt][nt][3] + bias[nt].y);
            *reinterpret_cast<__half2*>(&sv[r0 * ORS + col])       = lo;
            *reinterpret_cast<__half2*>(&sv[(r0 + 8) * ORS + col]) = hi;
        }
    }
    __syncthreads();
    #pragma unroll
    for (int i = 0; i < 8; i++) {              // 4096 uint4 = 128 rows x 32
        const int idx = i * NTHREADS + tid;
        const int row = idx >> 5, c = idx & 31;
        uint4 v = *reinterpret_cast<const uint4*>(&sv[row * ORS + c * 8]);
        *reinterpret_cast<uint4*>(&g_v16[(size_t)(bm + row) * NB + bn + c * 8]) = v;
    }
}

// ---------------- LayerNorm-LSTM pointwise kernel (round-15 best) ----------------
__device__ __forceinline__ float ftanh(float x) {
    float r;
    asm("tanh.approx.f32 %0, %1;" : "=f"(r) : "f"(x));
    return r;
}
__device__ __forceinline__ float fsig(float x) {
    return fmaf(0.5f, ftanh(0.5f * x), 0.5f);   // sigmoid via HW tanh
}

__global__ __launch_bounds__(256, 6)
void ln_lstm_kernel(const float* __restrict__ cprev,
                    const float* __restrict__ gamma_ifgo, const float* __restrict__ beta_ifgo,
                    const float* __restrict__ gamma_c,    const float* __restrict__ beta_c,
                    float* __restrict__ out_h, float* __restrict__ out_c)
{
    const float EPS = 1e-6f;
    const int b   = blockIdx.x;
    const int tid = threadIdx.x;
    const int warp = tid >> 5, lane = tid & 31;

    const uint2* vb2 = reinterpret_cast<const uint2*>(g_v16 + (size_t)b * NB);
    const float4* ga4 = reinterpret_cast<const float4*>(gamma_ifgo);
    const float4* be4 = reinterpret_cast<const float4*>(beta_ifgo);
    const float4* gc4 = reinterpret_cast<const float4*>(gamma_c);
    const float4* bc4 = reinterpret_cast<const float4*>(beta_c);
    const float4* cp4 = reinterpret_cast<const float4*>(cprev) + (size_t)b * 256;
    float4* oh4 = reinterpret_cast<float4*>(out_h) + (size_t)b * 256;
    float4* oc4 = reinterpret_cast<float4*>(out_c) + (size_t)b * 256;

    float4 val[4];
    float s[4], q[4];
    #pragma unroll
    for (int g = 0; g < 4; g++) {
        uint2 raw = vb2[g * 256 + tid];
        float2 p01 = __half22float2(*reinterpret_cast<__half2*>(&raw.x));
        float2 p23 = __half22float2(*reinterpret_cast<__half2*>(&raw.y));
        float4 v = make_float4(p01.x, p01.y, p23.x, p23.y);
        val[g] = v;
        s[g] = v.x + v.y + v.z + v.w;
        q[g] = v.x * v.x + v.y * v.y + v.z * v.z + v.w * v.w;
    }

    __shared__ float red[8][8];
    __shared__ float red2[8][2];
    __shared__ float mean_s[4], inv_s[4];

    #pragma unroll
    for (int g = 0; g < 4; g++)
        #pragma unroll
        for (int off = 16; off; off >>= 1) {
            s[g] += __shfl_xor_sync(0xffffffffu, s[g], off);
            q[g] += __shfl_xor_sync(0xffffffffu, q[g], off);
        }
    if (lane == 0) {
        #pragma unroll
        for (int g = 0; g < 4; g++) { red[warp][g] = s[g]; red[warp][g + 4] = q[g]; }
    }
    __syncthreads();
    if (tid < 4) {
        float ts = 0.f, tq2 = 0.f;
        #pragma unroll
        for (int w = 0; w < 8; w++) { ts += red[w][tid]; tq2 += red[w][tid + 4]; }
        float mean = ts * (1.f / HD);
        float var  = (tq2 - (float)HD * mean * mean) * (1.f / (HD - 1));
        var = fmaxf(var, 0.f);
        mean_s[tid] = mean;
        inv_s[tid]  = 1.f / (sqrtf(var) + EPS);
    }
    __syncthreads();

    float4 gam[4], bet[4];
    #pragma unroll
    for (int g = 0; g < 4; g++) { gam[g] = ga4[g * 256 + tid]; bet[g] = be4[g * 256 + tid]; }
    const float4 cpv = cp4[tid];

    float ivals[4], fvals[4], gvals[4], ovals[4];
    {
        const float m0 = mean_s[0], m1 = mean_s[1], m2 = mean_s[2], m3 = mean_s[3];
        const float i0 = inv_s[0],  i1 = inv_s[1],  i2 = inv_s[2],  i3 = inv_s[3];
        const float* v0 = &val[0].x; const float* v1 = &val[1].x;
        const float* v2 = &val[2].x; const float* v3 = &val[3].x;
        const float* g0 = &gam[0].x; const float* g1 = &gam[1].x;
        const float* g2 = &gam[2].x; const float* g3 = &gam[3].x;
        const float* b0 = &bet[0].x; const float* b1 = &bet[1].x;
        const float* b2 = &bet[2].x; const float* b3 = &bet[3].x;
        #pragma unroll
        for (int e = 0; e < 4; e++) {
            ivals[e] = (v0[e] - m0) * i0 * g0[e] + b0[e];
            fvals[e] = (v1[e] - m1) * i1 * g1[e] + b1[e] + 1.0f;
            gvals[e] = (v2[e] - m2) * i2 * g2[e] + b2[e];
            ovals[e] = (v3[e] - m3) * i3 * g3[e] + b3[e];
        }
    }

    float nc[4];
    float cs = 0.f, cq = 0.f;
    const float* cpe = &cpv.x;
    #pragma unroll
    for (int e = 0; e < 4; e++) {
        float ncr = cpe[e] * fsig(fvals[e]) + fsig(ivals[e]) * ftanh(gvals[e]);
        nc[e] = ncr;
        cs += ncr;
        cq += ncr * ncr;
    }

    #pragma unroll
    for (int off = 16; off; off >>= 1) {
        cs += __shfl_xor_sync(0xffffffffu, cs, off);
        cq += __shfl_xor_sync(0xffffffffu, cq, off);
    }
    if (lane == 0) { red2[warp][0] = cs; red2[warp][1] = cq; }   // separate buffer: no pre-barrier
    __syncthreads();
    __shared__ float meanc_s, invc_s;
    if (tid == 0) {
        float ts = 0.f, tq2 = 0.f;
        #pragma unroll
        for (int w = 0; w < 8; w++) { ts += red2[w][0]; tq2 += red2[w][1]; }
        float mean = ts * (1.f / HD);
        float var  = (tq2 - (float)HD * mean * mean) * (1.f / (HD - 1));
        var = fmaxf(var, 0.f);
        meanc_s = mean;
        invc_s  = 1.f / (sqrtf(var) + EPS);
    }
    __syncthreads();
    const float mc = meanc_s, ic = invc_s;

    const float4 gcv = gc4[tid], bcv = bc4[tid];
    const float* gce = &gcv.x; const float* bce = &bcv.x;
    float4 outc, outh;
    float* ocp = &outc.x; float* ohp = &outh.x;
    #pragma unroll
    for (int e = 0; e < 4; e++) {
        float ncn = (nc[e] - mc) * ic * gce[e] + bce[e];
        ocp[e] = ncn;
        ohp[e] = ftanh(ncn) * fsig(ovals[e]);
    }
    oc4[tid] = outc;
    oh4[tid] = outh;
}

extern "C" void kernel_launch(void* const* d_in, const int* in_sizes, int n_in,
                              void* d_out, int out_size)
{
    const float* x          = (const float*)d_in[0];
    const float* h          = (const float*)d_in[1];
    const float* c          = (const float*)d_in[2];
    const float* w_ih       = (const float*)d_in[3];
    const float* b_ih       = (const float*)d_in[4];
    const float* w_hh       = (const float*)d_in[5];
    const float* gamma_ifgo = (const float*)d_in[6];
    const float* beta_ifgo  = (const float*)d_in[7];
    const float* gamma_c    = (const float*)d_in[8];
    const float* beta_c     = (const float*)d_in[9];

    float* out_h = (float*)d_out;
    float* out_c = out_h + (size_t)MB * HD;

    cudaFuncSetAttribute(gemm_f16_kernel,
                         cudaFuncAttributeMaxDynamicSharedMemorySize, SMEM_TOTAL);

    cvt_all_kernel<<<1536, 512>>>((const float4*)x, (const float4*)h,
                                  (const float4*)w_ih, (const float4*)w_hh);

    dim3 ggrid(NB / BN, MB / BM);   // 16 x 64
    gemm_f16_kernel<<<ggrid, NTHREADS, SMEM_TOTAL>>>(b_ih);
    ln_lstm_kernel<<<MB, 256>>>(c, gamma_ifgo, beta_ifgo, gamma_c, beta_c, out_h, out_c);
}